// round 4
// baseline (speedup 1.0000x reference)
#include <cuda_runtime.h>

#define NMAX 50000
#define EMAX 800000
#define DINC 128
#define HH 4
#define CC 32
#define ED 16
#define NEG 0.2f
#define LNEPS 1e-5f

// ---------------- scratch (static device globals) ---------------------------
__device__ __align__(16) float g_h[(size_t)NMAX * DINC];     // 25.6 MB
__device__ __align__(16) float g_asrc[NMAX * HH];
__device__ __align__(16) float g_adst[NMAX * HH];
__device__ __align__(16) float g_ae[(size_t)EMAX * HH];      // 12.8 MB
__device__ __align__(16) float g_loop[NMAX * ED];            // 3.2 MB
__device__ int   g_degi[NMAX];
__device__ int   g_start[NMAX];
__device__ int   g_cursor[NMAX];
__device__ float g_v[ED * HH];
__device__ __align__(8) int2 g_sd[EMAX];                     // (src,dst)
__device__ __align__(8) int2 g_csr[EMAX];                    // (src,eid) CSR by dst

// ---------------- kzero: zero loop_attr and degi -----------------------------
__global__ void kzero(int n) {
    int total = n * ED + n;
    for (int i = blockIdx.x * blockDim.x + threadIdx.x; i < total;
         i += gridDim.x * blockDim.x) {
        if (i < n * ED) g_loop[i] = 0.f;
        else            g_degi[i - n * ED] = 0;
    }
}

// ---------------- kvinit: v[k][h] = sum_c W_edge[k,h*32+c]*att_edge[h,c] ----
__global__ void kvinit(const float* __restrict__ W_edge,
                       const float* __restrict__ att_edge) {
    int t = threadIdx.x;
    if (t >= ED * HH) return;
    int k = t >> 2, h = t & 3;
    float s = 0.f;
    #pragma unroll
    for (int c = 0; c < CC; c++)
        s += W_edge[k * (HH * CC) + h * CC + c] * att_edge[h * CC + c];
    g_v[k * HH + h] = s;
}

// ---------------- K2: h = x@W_lin, a_src, a_dst -----------------------------
__global__ void k2_gemm(const float* __restrict__ x,
                        const float* __restrict__ Wlin,
                        const float* __restrict__ att_src,
                        const float* __restrict__ att_dst, int N) {
    __shared__ __align__(16) float sx[8][8][DINC];
    int w = threadIdx.x >> 5, lane = threadIdx.x & 31;
    const float4* W4 = (const float4*)Wlin;
    float4 a_s = __ldg((const float4*)&att_src[lane * 4]);
    float4 a_d = __ldg((const float4*)&att_dst[lane * 4]);
    int ngroups = (N + 63) >> 6;
    for (int g = blockIdx.x; g < ngroups; g += gridDim.x) {
        int r0 = g * 64 + w * 8;
        #pragma unroll
        for (int r = 0; r < 8; r++) {
            int n = r0 + r;
            if (n < N)
                *(float4*)&sx[w][r][lane * 4] =
                    __ldg((const float4*)&x[(size_t)n * DINC + lane * 4]);
        }
        __syncwarp();
        float4 acc[8];
        #pragma unroll
        for (int r = 0; r < 8; r++) acc[r] = make_float4(0.f, 0.f, 0.f, 0.f);
        #pragma unroll 2
        for (int kk = 0; kk < DINC; kk += 4) {
            float4 w0 = __ldg(&W4[(kk + 0) * 32 + lane]);
            float4 w1 = __ldg(&W4[(kk + 1) * 32 + lane]);
            float4 w2 = __ldg(&W4[(kk + 2) * 32 + lane]);
            float4 w3 = __ldg(&W4[(kk + 3) * 32 + lane]);
            #pragma unroll
            for (int r = 0; r < 8; r++) {
                float4 xv = *(const float4*)&sx[w][r][kk];
                acc[r].x += xv.x * w0.x; acc[r].y += xv.x * w0.y;
                acc[r].z += xv.x * w0.z; acc[r].w += xv.x * w0.w;
                acc[r].x += xv.y * w1.x; acc[r].y += xv.y * w1.y;
                acc[r].z += xv.y * w1.z; acc[r].w += xv.y * w1.w;
                acc[r].x += xv.z * w2.x; acc[r].y += xv.z * w2.y;
                acc[r].z += xv.z * w2.z; acc[r].w += xv.z * w2.w;
                acc[r].x += xv.w * w3.x; acc[r].y += xv.w * w3.y;
                acc[r].z += xv.w * w3.z; acc[r].w += xv.w * w3.w;
            }
        }
        int head = lane >> 3;
        #pragma unroll
        for (int r = 0; r < 8; r++) {
            int n = r0 + r;
            if (n < N) {
                *(float4*)&g_h[(size_t)n * DINC + lane * 4] = acc[r];
                float ps = acc[r].x * a_s.x + acc[r].y * a_s.y +
                           acc[r].z * a_s.z + acc[r].w * a_s.w;
                float pd = acc[r].x * a_d.x + acc[r].y * a_d.y +
                           acc[r].z * a_d.z + acc[r].w * a_d.w;
                #pragma unroll
                for (int o = 1; o < 8; o <<= 1) {
                    ps += __shfl_xor_sync(0xffffffffu, ps, o);
                    pd += __shfl_xor_sync(0xffffffffu, pd, o);
                }
                if ((lane & 7) == 0) {
                    g_asrc[n * HH + head] = ps;
                    g_adst[n * HH + head] = pd;
                }
            }
        }
        __syncwarp();
    }
}

// ---------------- K1: edge MLP + dtype detect + deg/loop atomics + a_e ------
__global__ void k1_edge_mlp(const float* __restrict__ eattr,
                            const void* __restrict__ ei,
                            const float* __restrict__ Wep,
                            const float* __restrict__ bep, int E) {
    __shared__ float sW[ED * ED];
    __shared__ float sb[ED];
    __shared__ int s_is64;
    int t = threadIdx.x;
    if (t == 0) s_is64 = 1;
    if (t < ED * ED) sW[t] = Wep[t];
    if (t < ED)      sb[t] = bep[t];
    int base = blockIdx.x * 256;
    int e = base + t;
    __syncthreads();
    // dtype probe: int64 (<2^31) data has 0 in every odd int32 word of src[].
    if (e < E && ((const int*)ei)[2 * e + 1] != 0) s_is64 = 0;
    __syncthreads();
    if (e >= E) return;

    int src, dst;
    if (s_is64) {
        const long long* p = (const long long*)ei;
        src = (int)p[e];
        dst = (int)p[(size_t)E + e];
    } else {
        const int* p = (const int*)ei;
        src = p[e];
        dst = p[(size_t)E + e];
    }
    g_sd[e] = make_int2(src, dst);

    const float4* ap = (const float4*)(eattr + (size_t)e * ED);
    float4 x0 = __ldg(ap + 0), x1 = __ldg(ap + 1);
    float4 x2 = __ldg(ap + 2), x3 = __ldg(ap + 3);
    float xin[ED] = {x0.x, x0.y, x0.z, x0.w, x1.x, x1.y, x1.z, x1.w,
                     x2.x, x2.y, x2.z, x2.w, x3.x, x3.y, x3.z, x3.w};
    float ea[ED];
    #pragma unroll
    for (int k = 0; k < ED; k++) ea[k] = sb[k];
    #pragma unroll
    for (int j = 0; j < ED; j++) {
        float a = xin[j];
        #pragma unroll
        for (int k = 0; k < ED; k++) ea[k] += a * sW[j * ED + k];
    }
    #pragma unroll
    for (int k = 0; k < ED; k++) ea[k] = fmaxf(ea[k], 0.f);

    float ae[HH] = {0.f, 0.f, 0.f, 0.f};
    #pragma unroll
    for (int k = 0; k < ED; k++) {
        float a = ea[k];
        #pragma unroll
        for (int h = 0; h < HH; h++) ae[h] += a * g_v[k * HH + h];
    }
    *(float4*)&g_ae[(size_t)e * 4] = make_float4(ae[0], ae[1], ae[2], ae[3]);
    atomicAdd(&g_degi[dst], 1);
    float* lp = &g_loop[(size_t)dst * ED];
    #pragma unroll
    for (int q = 0; q < 4; q++) {
        asm volatile("red.global.add.v4.f32 [%0], {%1,%2,%3,%4};" ::
                     "l"(lp + 4 * q),
                     "f"(ea[4 * q + 0]), "f"(ea[4 * q + 1]),
                     "f"(ea[4 * q + 2]), "f"(ea[4 * q + 3]) : "memory");
    }
}

// ---------------- kscan: exclusive prefix sum over degrees (single block) ---
__global__ void kscan(int N) {
    __shared__ int part[1024];
    int t = threadIdx.x;
    int chunk = (N + 1023) >> 10;
    int lo = t * chunk, hi = min(lo + chunk, N);
    int s = 0;
    for (int i = lo; i < hi; i++) s += g_degi[i];
    part[t] = s;
    __syncthreads();
    // inclusive Hillis-Steele scan
    for (int off = 1; off < 1024; off <<= 1) {
        int v = (t >= off) ? part[t - off] : 0;
        __syncthreads();
        part[t] += v;
        __syncthreads();
    }
    int run = (t == 0) ? 0 : part[t - 1];
    for (int i = lo; i < hi; i++) {
        g_start[i]  = run;
        g_cursor[i] = run;
        run += g_degi[i];
    }
}

// ---------------- kfill: bucket edges into CSR -------------------------------
__global__ void kfill(int E) {
    int e = blockIdx.x * blockDim.x + threadIdx.x;
    if (e >= E) return;
    int2 sd = g_sd[e];
    int pos = atomicAdd(&g_cursor[sd.y], 1);
    g_csr[pos] = make_int2(sd.x, e);
}

// ---------------- K6: gather + softmax-normalize + bias + residual + LN -----
// One 128-thread block per node; thread t owns channel t, head = t>>5.
__global__ void k6_gather(float* __restrict__ out, const float* __restrict__ x,
                          const float* __restrict__ bias,
                          const float* __restrict__ lng,
                          const float* __restrict__ lnb, int N) {
    int n = blockIdx.x;
    int t = threadIdx.x;
    int head = t >> 5;
    __shared__ float sv[ED * HH];
    __shared__ float sla[ED];
    __shared__ float red[8];
    if (t < ED * HH) sv[t] = g_v[t];
    int degi = g_degi[n];
    if (t < ED) {
        float d = (float)max(degi, 1);
        sla[t] = g_loop[(size_t)n * ED + t] / d;
    }
    __syncthreads();

    // self-loop term
    float ael = 0.f;
    #pragma unroll
    for (int k = 0; k < ED; k++) ael += sla[k] * sv[k * HH + head];
    float adst_h = __ldg(&g_adst[n * HH + head]);
    float al = __ldg(&g_asrc[n * HH + head]) + adst_h + ael;
    al = (al >= 0.f) ? al : NEG * al;
    float ex = __expf(al);
    float acc = ex * g_h[(size_t)n * DINC + t];
    float den = ex;

    // incoming edges
    int p = g_start[n], pend = p + degi;
    for (; p < pend; p++) {
        int2 se = __ldg(&g_csr[p]);
        float a = __ldg(&g_asrc[se.x * HH + head]) + adst_h +
                  __ldg(&g_ae[(size_t)se.y * HH + head]);
        a = (a >= 0.f) ? a : NEG * a;
        float wgt = __expf(a);
        acc += wgt * __ldg(&g_h[(size_t)se.x * DINC + t]);
        den += wgt;
    }

    float v = acc / den + __ldg(&bias[t]) + __ldg(&x[(size_t)n * DINC + t]);

    // LayerNorm over 128 channels
    float s = v, s2 = v * v;
    #pragma unroll
    for (int o = 16; o > 0; o >>= 1) {
        s  += __shfl_xor_sync(0xffffffffu, s, o);
        s2 += __shfl_xor_sync(0xffffffffu, s2, o);
    }
    if ((t & 31) == 0) { red[head] = s; red[4 + head] = s2; }
    __syncthreads();
    s  = red[0] + red[1] + red[2] + red[3];
    s2 = red[4] + red[5] + red[6] + red[7];
    float mu  = s * (1.f / 128.f);
    float var = s2 * (1.f / 128.f) - mu * mu;
    float r = rsqrtf(var + LNEPS);
    out[(size_t)n * DINC + t] = (v - mu) * r * __ldg(&lng[t]) + __ldg(&lnb[t]);
}

// ---------------- launch -----------------------------------------------------
extern "C" void kernel_launch(void* const* d_in, const int* in_sizes, int n_in,
                              void* d_out, int out_size) {
    const float* x        = (const float*)d_in[0];
    const void*  ei       = (const void*)d_in[1];
    const float* eattr    = (const float*)d_in[2];
    const float* Wep      = (const float*)d_in[3];
    const float* bep      = (const float*)d_in[4];
    const float* Wlin     = (const float*)d_in[5];
    const float* Wedge    = (const float*)d_in[6];
    const float* att_src  = (const float*)d_in[7];
    const float* att_dst  = (const float*)d_in[8];
    const float* att_edge = (const float*)d_in[9];
    const float* bias     = (const float*)d_in[10];
    const float* lng      = (const float*)d_in[11];
    const float* lnb      = (const float*)d_in[12];
    float* out = (float*)d_out;

    int N = in_sizes[0] / DINC;
    int E = in_sizes[2] / ED;

    kzero<<<512, 1024>>>(N);                                       // 1
    kvinit<<<1, 64>>>(Wedge, att_edge);                            // 2
    k1_edge_mlp<<<(E + 255) / 256, 256>>>(eattr, ei, Wep, bep, E); // 3
    k2_gemm<<<592, 256>>>(x, Wlin, att_src, att_dst, N);           // 4
    kscan<<<1, 1024>>>(N);                                         // 5
    kfill<<<(E + 255) / 256, 256>>>(E);                            // 6
    k6_gather<<<N, 128>>>(out, x, bias, lng, lnb, N);              // 7
}

// round 5
// speedup vs baseline: 1.1540x; 1.1540x over previous
#include <cuda_runtime.h>

#define NMAX 50000
#define EMAX 800000
#define DINC 128
#define HH 4
#define CC 32
#define ED 16
#define NEG 0.2f
#define LNEPS 1e-5f
#define CHUNK 128

// ---------------- scratch (static device globals) ---------------------------
__device__ __align__(16) float g_h[(size_t)NMAX * DINC];     // 25.6 MB
__device__ __align__(16) float g_asrc[NMAX * HH];
__device__ __align__(16) float g_adst[NMAX * HH];
__device__ __align__(16) float g_ae[(size_t)EMAX * HH];      // 12.8 MB
__device__ int   g_degi[NMAX];
__device__ int   g_start[NMAX];
__device__ int   g_cursor[NMAX];
__device__ float g_v[ED * HH];
__device__ __align__(8) int2 g_sd[EMAX];                     // (src,dst)
__device__ __align__(8) int2 g_csr[EMAX];                    // (src,eid) CSR by dst

// ---------------- kzero: zero integer degrees -------------------------------
__global__ void kzero(int n) {
    int i = blockIdx.x * blockDim.x + threadIdx.x;
    if (i < n) g_degi[i] = 0;
}

// ---------------- kvinit: v[k][h] = sum_c W_edge[k,h*32+c]*att_edge[h,c] ----
__global__ void kvinit(const float* __restrict__ W_edge,
                       const float* __restrict__ att_edge) {
    int t = threadIdx.x;
    if (t >= ED * HH) return;
    int k = t >> 2, h = t & 3;
    float s = 0.f;
    #pragma unroll
    for (int c = 0; c < CC; c++)
        s += W_edge[k * (HH * CC) + h * CC + c] * att_edge[h * CC + c];
    g_v[k * HH + h] = s;
}

// ---------------- K1: edge MLP + dtype detect + a_e + degree ----------------
__global__ void k1_edge_mlp(const float* __restrict__ eattr,
                            const void* __restrict__ ei,
                            const float* __restrict__ Wep,
                            const float* __restrict__ bep, int E) {
    __shared__ float sW[ED * ED];
    __shared__ float sb[ED];
    __shared__ float sv[ED * HH];
    __shared__ int s_is64;
    int t = threadIdx.x;
    if (t == 0) s_is64 = 1;
    if (t < ED * ED) sW[t] = Wep[t];
    if (t < ED)      sb[t] = bep[t];
    if (t < ED * HH) sv[t] = g_v[t];
    int base = blockIdx.x * 256;
    int e = base + t;
    __syncthreads();
    // dtype probe: int64 (<2^31) data has 0 in every odd int32 word of src[].
    if (e < E && ((const int*)ei)[2 * e + 1] != 0) s_is64 = 0;
    __syncthreads();
    if (e >= E) return;

    int src, dst;
    if (s_is64) {
        const long long* p = (const long long*)ei;
        src = (int)p[e];
        dst = (int)p[(size_t)E + e];
    } else {
        const int* p = (const int*)ei;
        src = p[e];
        dst = p[(size_t)E + e];
    }
    g_sd[e] = make_int2(src, dst);

    const float4* ap = (const float4*)(eattr + (size_t)e * ED);
    float4 x0 = __ldg(ap + 0), x1 = __ldg(ap + 1);
    float4 x2 = __ldg(ap + 2), x3 = __ldg(ap + 3);
    float xin[ED] = {x0.x, x0.y, x0.z, x0.w, x1.x, x1.y, x1.z, x1.w,
                     x2.x, x2.y, x2.z, x2.w, x3.x, x3.y, x3.z, x3.w};
    float ea[ED];
    #pragma unroll
    for (int k = 0; k < ED; k++) ea[k] = sb[k];
    #pragma unroll
    for (int j = 0; j < ED; j++) {
        float a = xin[j];
        #pragma unroll
        for (int k = 0; k < ED; k++) ea[k] += a * sW[j * ED + k];
    }
    float ae[HH] = {0.f, 0.f, 0.f, 0.f};
    #pragma unroll
    for (int k = 0; k < ED; k++) {
        float a = fmaxf(ea[k], 0.f);
        #pragma unroll
        for (int h = 0; h < HH; h++) ae[h] += a * sv[k * HH + h];
    }
    *(float4*)&g_ae[(size_t)e * 4] = make_float4(ae[0], ae[1], ae[2], ae[3]);
    atomicAdd(&g_degi[dst], 1);
}

// ---------------- K2: h = x@W_lin, a_src, a_dst -----------------------------
__global__ void k2_gemm(const float* __restrict__ x,
                        const float* __restrict__ Wlin,
                        const float* __restrict__ att_src,
                        const float* __restrict__ att_dst, int N) {
    __shared__ __align__(16) float sx[8][8][DINC];
    int w = threadIdx.x >> 5, lane = threadIdx.x & 31;
    const float4* W4 = (const float4*)Wlin;
    float4 a_s = __ldg((const float4*)&att_src[lane * 4]);
    float4 a_d = __ldg((const float4*)&att_dst[lane * 4]);
    int ngroups = (N + 63) >> 6;
    for (int g = blockIdx.x; g < ngroups; g += gridDim.x) {
        int r0 = g * 64 + w * 8;
        #pragma unroll
        for (int r = 0; r < 8; r++) {
            int n = r0 + r;
            if (n < N)
                *(float4*)&sx[w][r][lane * 4] =
                    __ldg((const float4*)&x[(size_t)n * DINC + lane * 4]);
        }
        __syncwarp();
        float4 acc[8];
        #pragma unroll
        for (int r = 0; r < 8; r++) acc[r] = make_float4(0.f, 0.f, 0.f, 0.f);
        #pragma unroll 2
        for (int kk = 0; kk < DINC; kk += 4) {
            float4 w0 = __ldg(&W4[(kk + 0) * 32 + lane]);
            float4 w1 = __ldg(&W4[(kk + 1) * 32 + lane]);
            float4 w2 = __ldg(&W4[(kk + 2) * 32 + lane]);
            float4 w3 = __ldg(&W4[(kk + 3) * 32 + lane]);
            #pragma unroll
            for (int r = 0; r < 8; r++) {
                float4 xv = *(const float4*)&sx[w][r][kk];
                acc[r].x += xv.x * w0.x; acc[r].y += xv.x * w0.y;
                acc[r].z += xv.x * w0.z; acc[r].w += xv.x * w0.w;
                acc[r].x += xv.y * w1.x; acc[r].y += xv.y * w1.y;
                acc[r].z += xv.y * w1.z; acc[r].w += xv.y * w1.w;
                acc[r].x += xv.z * w2.x; acc[r].y += xv.z * w2.y;
                acc[r].z += xv.z * w2.z; acc[r].w += xv.z * w2.w;
                acc[r].x += xv.w * w3.x; acc[r].y += xv.w * w3.y;
                acc[r].z += xv.w * w3.z; acc[r].w += xv.w * w3.w;
            }
        }
        int head = lane >> 3;
        #pragma unroll
        for (int r = 0; r < 8; r++) {
            int n = r0 + r;
            if (n < N) {
                *(float4*)&g_h[(size_t)n * DINC + lane * 4] = acc[r];
                float ps = acc[r].x * a_s.x + acc[r].y * a_s.y +
                           acc[r].z * a_s.z + acc[r].w * a_s.w;
                float pd = acc[r].x * a_d.x + acc[r].y * a_d.y +
                           acc[r].z * a_d.z + acc[r].w * a_d.w;
                #pragma unroll
                for (int o = 1; o < 8; o <<= 1) {
                    ps += __shfl_xor_sync(0xffffffffu, ps, o);
                    pd += __shfl_xor_sync(0xffffffffu, pd, o);
                }
                if ((lane & 7) == 0) {
                    g_asrc[n * HH + head] = ps;
                    g_adst[n * HH + head] = pd;
                }
            }
        }
        __syncwarp();
    }
}

// ---------------- kscan: exclusive prefix sum over degrees (single block) ---
__global__ void kscan(int N) {
    __shared__ int part[1024];
    int t = threadIdx.x;
    int chunk = (N + 1023) >> 10;
    int lo = t * chunk, hi = min(lo + chunk, N);
    int s = 0;
    for (int i = lo; i < hi; i++) s += g_degi[i];
    part[t] = s;
    __syncthreads();
    for (int off = 1; off < 1024; off <<= 1) {
        int v = (t >= off) ? part[t - off] : 0;
        __syncthreads();
        part[t] += v;
        __syncthreads();
    }
    int run = (t == 0) ? 0 : part[t - 1];
    for (int i = lo; i < hi; i++) {
        g_start[i]  = run;
        g_cursor[i] = run;
        run += g_degi[i];
    }
}

// ---------------- kfill: bucket edges into CSR -------------------------------
__global__ void kfill(int E) {
    int e = blockIdx.x * blockDim.x + threadIdx.x;
    if (e >= E) return;
    int2 sd = g_sd[e];
    int pos = atomicAdd(&g_cursor[sd.y], 1);
    g_csr[pos] = make_int2(sd.x, e);
}

// ---------------- K6: two-phase gather + self-loop + LN ---------------------
// One 128-thread block per node; thread t owns channel t, head = t>>5.
__global__ void k6_gather(float* __restrict__ out, const float* __restrict__ x,
                          const float* __restrict__ bias,
                          const float* __restrict__ lng,
                          const float* __restrict__ lnb, int N) {
    int n = blockIdx.x;
    int t = threadIdx.x;
    int head = t >> 5;
    __shared__ int   ssrc[CHUNK];
    __shared__ float swgt[CHUNK * 4];
    __shared__ float red[16];

    int deg   = g_degi[n];
    int start = g_start[n];
    float4 adst = *(const float4*)&g_adst[(size_t)n * 4];   // broadcast

    float acc = 0.f, den = 0.f;
    float4 aesum = make_float4(0.f, 0.f, 0.f, 0.f);

    for (int c0 = 0; c0 < deg; c0 += CHUNK) {
        int m = min(CHUNK, deg - c0);
        // ---- Phase A: weights for this chunk (one edge per thread) ----
        if (t < m) {
            int2 se = __ldg(&g_csr[start + c0 + t]);
            float4 as = __ldg((const float4*)&g_asrc[(size_t)se.x * 4]);
            float4 ae = __ldg((const float4*)&g_ae[(size_t)se.y * 4]);
            aesum.x += ae.x; aesum.y += ae.y; aesum.z += ae.z; aesum.w += ae.w;
            float a0 = as.x + adst.x + ae.x, a1 = as.y + adst.y + ae.y;
            float a2 = as.z + adst.z + ae.z, a3 = as.w + adst.w + ae.w;
            a0 = (a0 >= 0.f) ? a0 : NEG * a0;  a1 = (a1 >= 0.f) ? a1 : NEG * a1;
            a2 = (a2 >= 0.f) ? a2 : NEG * a2;  a3 = (a3 >= 0.f) ? a3 : NEG * a3;
            ssrc[t] = se.x;
            swgt[t * 4 + 0] = __expf(a0);
            swgt[t * 4 + 1] = __expf(a1);
            swgt[t * 4 + 2] = __expf(a2);
            swgt[t * 4 + 3] = __expf(a3);
        }
        __syncthreads();
        // ---- Phase B: accumulate (broadcast LDS + independent LDG) ----
        int p = 0;
        for (; p + 4 <= m; p += 4) {
            int s0 = ssrc[p], s1 = ssrc[p + 1], s2 = ssrc[p + 2], s3 = ssrc[p + 3];
            float w0 = swgt[(p + 0) * 4 + head];
            float w1 = swgt[(p + 1) * 4 + head];
            float w2 = swgt[(p + 2) * 4 + head];
            float w3 = swgt[(p + 3) * 4 + head];
            float h0 = __ldg(&g_h[(size_t)s0 * DINC + t]);
            float h1 = __ldg(&g_h[(size_t)s1 * DINC + t]);
            float h2 = __ldg(&g_h[(size_t)s2 * DINC + t]);
            float h3 = __ldg(&g_h[(size_t)s3 * DINC + t]);
            acc += w0 * h0; den += w0;
            acc += w1 * h1; den += w1;
            acc += w2 * h2; den += w2;
            acc += w3 * h3; den += w3;
        }
        for (; p < m; p++) {
            int s0 = ssrc[p];
            float w0 = swgt[p * 4 + head];
            acc += w0 * __ldg(&g_h[(size_t)s0 * DINC + t]);
            den += w0;
        }
        __syncthreads();
    }

    // ---- block-reduce aesum (each edge counted once) ----
    #pragma unroll
    for (int o = 16; o > 0; o >>= 1) {
        aesum.x += __shfl_xor_sync(0xffffffffu, aesum.x, o);
        aesum.y += __shfl_xor_sync(0xffffffffu, aesum.y, o);
        aesum.z += __shfl_xor_sync(0xffffffffu, aesum.z, o);
        aesum.w += __shfl_xor_sync(0xffffffffu, aesum.w, o);
    }
    if ((t & 31) == 0) *(float4*)&red[(t >> 5) * 4] = aesum;
    __syncthreads();
    float aes = red[0 * 4 + head] + red[1 * 4 + head] +
                red[2 * 4 + head] + red[3 * 4 + head];

    // ---- self-loop term: ael = mean(a_e over incoming) ----
    float ael = aes / (float)max(deg, 1);
    float adst_h = (head == 0) ? adst.x : (head == 1) ? adst.y :
                   (head == 2) ? adst.z : adst.w;
    float al = __ldg(&g_asrc[(size_t)n * 4 + head]) + adst_h + ael;
    al = (al >= 0.f) ? al : NEG * al;
    float ex = __expf(al);
    acc += ex * g_h[(size_t)n * DINC + t];
    den += ex;

    float v = acc / den + __ldg(&bias[t]) + __ldg(&x[(size_t)n * DINC + t]);

    // ---- LayerNorm over 128 channels ----
    float s = v, s2 = v * v;
    #pragma unroll
    for (int o = 16; o > 0; o >>= 1) {
        s  += __shfl_xor_sync(0xffffffffu, s, o);
        s2 += __shfl_xor_sync(0xffffffffu, s2, o);
    }
    __syncthreads();   // red[] reuse
    if ((t & 31) == 0) { red[t >> 5] = s; red[4 + (t >> 5)] = s2; }
    __syncthreads();
    s  = red[0] + red[1] + red[2] + red[3];
    s2 = red[4] + red[5] + red[6] + red[7];
    float mu  = s * (1.f / 128.f);
    float var = s2 * (1.f / 128.f) - mu * mu;
    float r = rsqrtf(var + LNEPS);
    out[(size_t)n * DINC + t] = (v - mu) * r * __ldg(&lng[t]) + __ldg(&lnb[t]);
}

// ---------------- launch -----------------------------------------------------
extern "C" void kernel_launch(void* const* d_in, const int* in_sizes, int n_in,
                              void* d_out, int out_size) {
    const float* x        = (const float*)d_in[0];
    const void*  ei       = (const void*)d_in[1];
    const float* eattr    = (const float*)d_in[2];
    const float* Wep      = (const float*)d_in[3];
    const float* bep      = (const float*)d_in[4];
    const float* Wlin     = (const float*)d_in[5];
    const float* Wedge    = (const float*)d_in[6];
    const float* att_src  = (const float*)d_in[7];
    const float* att_dst  = (const float*)d_in[8];
    const float* att_edge = (const float*)d_in[9];
    const float* bias     = (const float*)d_in[10];
    const float* lng      = (const float*)d_in[11];
    const float* lnb      = (const float*)d_in[12];
    float* out = (float*)d_out;

    int N = in_sizes[0] / DINC;
    int E = in_sizes[2] / ED;

    kzero<<<(N + 1023) / 1024, 1024>>>(N);                         // 1
    kvinit<<<1, 64>>>(Wedge, att_edge);                            // 2
    k1_edge_mlp<<<(E + 255) / 256, 256>>>(eattr, ei, Wep, bep, E); // 3
    k2_gemm<<<592, 256>>>(x, Wlin, att_src, att_dst, N);           // 4
    kscan<<<1, 1024>>>(N);                                         // 5
    kfill<<<(E + 255) / 256, 256>>>(E);                            // 6
    k6_gather<<<N, 128>>>(out, x, bias, lng, lnb, N);              // 7
}

// round 6
// speedup vs baseline: 1.4085x; 1.2205x over previous
#include <cuda_runtime.h>

#define NMAX 50000
#define EMAX 800000
#define DINC 128
#define HH 4
#define CC 32
#define ED 16
#define NEG 0.2f
#define LNEPS 1e-5f

// ---------------- scratch (static device globals) ---------------------------
__device__ __align__(16) float g_h[(size_t)NMAX * DINC];     // 25.6 MB
__device__ __align__(16) float g_asrc[NMAX * HH];
__device__ __align__(16) float g_adst[NMAX * HH];
__device__ __align__(16) float g_ae[(size_t)EMAX * HH];      // 12.8 MB
__device__ int   g_degi[NMAX];
__device__ int   g_start[NMAX];
__device__ int   g_cursor[NMAX];
__device__ float g_v[ED * HH];
__device__ __align__(8) int2 g_sd[EMAX];                     // (src,dst)
__device__ __align__(8) int2 g_csr[EMAX];                    // (src,eid) CSR by dst

// ---------------- kinit: zero degrees + compute v ----------------------------
__global__ void kinit(const float* __restrict__ W_edge,
                      const float* __restrict__ att_edge, int n) {
    int i = blockIdx.x * blockDim.x + threadIdx.x;
    if (i < n) g_degi[i] = 0;
    if (blockIdx.x == 0 && threadIdx.x < ED * HH) {
        int k = threadIdx.x >> 2, h = threadIdx.x & 3;
        float s = 0.f;
        #pragma unroll
        for (int c = 0; c < CC; c++)
            s += W_edge[k * (HH * CC) + h * CC + c] * att_edge[h * CC + c];
        g_v[k * HH + h] = s;
    }
}

// ---------------- K1: edge MLP + dtype detect + a_e + degree ----------------
__global__ void k1_edge_mlp(const float* __restrict__ eattr,
                            const void* __restrict__ ei,
                            const float* __restrict__ Wep,
                            const float* __restrict__ bep, int E) {
    __shared__ float sW[ED * ED];
    __shared__ float sb[ED];
    __shared__ float sv[ED * HH];
    __shared__ int s_is64;
    int t = threadIdx.x;
    if (t == 0) s_is64 = 1;
    if (t < ED * ED) sW[t] = Wep[t];
    if (t < ED)      sb[t] = bep[t];
    if (t < ED * HH) sv[t] = g_v[t];
    int base = blockIdx.x * 256;
    int e = base + t;
    __syncthreads();
    // dtype probe: int64 (<2^31) data has 0 in every odd int32 word of src[].
    if (e < E && ((const int*)ei)[2 * e + 1] != 0) s_is64 = 0;
    __syncthreads();
    if (e >= E) return;

    int src, dst;
    if (s_is64) {
        const long long* p = (const long long*)ei;
        src = (int)p[e];
        dst = (int)p[(size_t)E + e];
    } else {
        const int* p = (const int*)ei;
        src = p[e];
        dst = p[(size_t)E + e];
    }
    g_sd[e] = make_int2(src, dst);

    const float4* ap = (const float4*)(eattr + (size_t)e * ED);
    float4 x0 = __ldg(ap + 0), x1 = __ldg(ap + 1);
    float4 x2 = __ldg(ap + 2), x3 = __ldg(ap + 3);
    float xin[ED] = {x0.x, x0.y, x0.z, x0.w, x1.x, x1.y, x1.z, x1.w,
                     x2.x, x2.y, x2.z, x2.w, x3.x, x3.y, x3.z, x3.w};
    float ea[ED];
    #pragma unroll
    for (int k = 0; k < ED; k++) ea[k] = sb[k];
    #pragma unroll
    for (int j = 0; j < ED; j++) {
        float a = xin[j];
        #pragma unroll
        for (int k = 0; k < ED; k++) ea[k] += a * sW[j * ED + k];
    }
    float ae[HH] = {0.f, 0.f, 0.f, 0.f};
    #pragma unroll
    for (int k = 0; k < ED; k++) {
        float a = fmaxf(ea[k], 0.f);
        #pragma unroll
        for (int h = 0; h < HH; h++) ae[h] += a * sv[k * HH + h];
    }
    *(float4*)&g_ae[(size_t)e * 4] = make_float4(ae[0], ae[1], ae[2], ae[3]);
    atomicAdd(&g_degi[dst], 1);
}

// ---------------- K2: h = x@W_lin, a_src, a_dst -----------------------------
__global__ void k2_gemm(const float* __restrict__ x,
                        const float* __restrict__ Wlin,
                        const float* __restrict__ att_src,
                        const float* __restrict__ att_dst, int N) {
    __shared__ __align__(16) float sx[8][8][DINC];
    int w = threadIdx.x >> 5, lane = threadIdx.x & 31;
    const float4* W4 = (const float4*)Wlin;
    float4 a_s = __ldg((const float4*)&att_src[lane * 4]);
    float4 a_d = __ldg((const float4*)&att_dst[lane * 4]);
    int ngroups = (N + 63) >> 6;
    for (int g = blockIdx.x; g < ngroups; g += gridDim.x) {
        int r0 = g * 64 + w * 8;
        #pragma unroll
        for (int r = 0; r < 8; r++) {
            int n = r0 + r;
            if (n < N)
                *(float4*)&sx[w][r][lane * 4] =
                    __ldg((const float4*)&x[(size_t)n * DINC + lane * 4]);
        }
        __syncwarp();
        float4 acc[8];
        #pragma unroll
        for (int r = 0; r < 8; r++) acc[r] = make_float4(0.f, 0.f, 0.f, 0.f);
        #pragma unroll 2
        for (int kk = 0; kk < DINC; kk += 4) {
            float4 w0 = __ldg(&W4[(kk + 0) * 32 + lane]);
            float4 w1 = __ldg(&W4[(kk + 1) * 32 + lane]);
            float4 w2 = __ldg(&W4[(kk + 2) * 32 + lane]);
            float4 w3 = __ldg(&W4[(kk + 3) * 32 + lane]);
            #pragma unroll
            for (int r = 0; r < 8; r++) {
                float4 xv = *(const float4*)&sx[w][r][kk];
                acc[r].x += xv.x * w0.x; acc[r].y += xv.x * w0.y;
                acc[r].z += xv.x * w0.z; acc[r].w += xv.x * w0.w;
                acc[r].x += xv.y * w1.x; acc[r].y += xv.y * w1.y;
                acc[r].z += xv.y * w1.z; acc[r].w += xv.y * w1.w;
                acc[r].x += xv.z * w2.x; acc[r].y += xv.z * w2.y;
                acc[r].z += xv.z * w2.z; acc[r].w += xv.z * w2.w;
                acc[r].x += xv.w * w3.x; acc[r].y += xv.w * w3.y;
                acc[r].z += xv.w * w3.z; acc[r].w += xv.w * w3.w;
            }
        }
        int head = lane >> 3;
        #pragma unroll
        for (int r = 0; r < 8; r++) {
            int n = r0 + r;
            if (n < N) {
                *(float4*)&g_h[(size_t)n * DINC + lane * 4] = acc[r];
                float ps = acc[r].x * a_s.x + acc[r].y * a_s.y +
                           acc[r].z * a_s.z + acc[r].w * a_s.w;
                float pd = acc[r].x * a_d.x + acc[r].y * a_d.y +
                           acc[r].z * a_d.z + acc[r].w * a_d.w;
                #pragma unroll
                for (int o = 1; o < 8; o <<= 1) {
                    ps += __shfl_xor_sync(0xffffffffu, ps, o);
                    pd += __shfl_xor_sync(0xffffffffu, pd, o);
                }
                if ((lane & 7) == 0) {
                    g_asrc[n * HH + head] = ps;
                    g_adst[n * HH + head] = pd;
                }
            }
        }
        __syncwarp();
    }
}

// ---------------- kscan: exclusive prefix sum over degrees (single block) ---
__global__ void kscan(int N) {
    __shared__ int part[1024];
    int t = threadIdx.x;
    int chunk = (N + 1023) >> 10;
    int lo = t * chunk, hi = min(lo + chunk, N);
    int s = 0;
    for (int i = lo; i < hi; i++) s += g_degi[i];
    part[t] = s;
    __syncthreads();
    for (int off = 1; off < 1024; off <<= 1) {
        int v = (t >= off) ? part[t - off] : 0;
        __syncthreads();
        part[t] += v;
        __syncthreads();
    }
    int run = (t == 0) ? 0 : part[t - 1];
    for (int i = lo; i < hi; i++) {
        g_start[i]  = run;
        g_cursor[i] = run;
        run += g_degi[i];
    }
}

// ---------------- kfill: bucket edges into CSR -------------------------------
__global__ void kfill(int E) {
    int e = blockIdx.x * blockDim.x + threadIdx.x;
    if (e >= E) return;
    int2 sd = g_sd[e];
    int pos = atomicAdd(&g_cursor[sd.y], 1);
    g_csr[pos] = make_int2(sd.x, e);
}

// ---------------- K6: warp-per-node gather + self-loop + LN ------------------
// One warp per node; lane owns 4 channels (float4 at lane*4), head = lane>>3.
__global__ void k6_gather(float* __restrict__ out, const float* __restrict__ x,
                          const float* __restrict__ bias,
                          const float* __restrict__ lng,
                          const float* __restrict__ lnb, int N) {
    int n = (int)((blockIdx.x * (size_t)blockDim.x + threadIdx.x) >> 5);
    int lane = threadIdx.x & 31;
    if (n >= N) return;
    int head = lane >> 3;

    int deg   = g_degi[n];
    int start = g_start[n];
    float4 adst = __ldg((const float4*)&g_adst[(size_t)n * 4]);

    float4 acc = make_float4(0.f, 0.f, 0.f, 0.f);
    float  den = 0.f;
    float4 aesum = make_float4(0.f, 0.f, 0.f, 0.f);

    for (int c0 = 0; c0 < deg; c0 += 32) {
        int m = min(32, deg - c0);
        // ---- Phase A: one edge per lane, all 4 head weights in registers ----
        int   esrc = 0;
        float4 w4 = make_float4(0.f, 0.f, 0.f, 0.f);
        if (lane < m) {
            int2 se = __ldg(&g_csr[start + c0 + lane]);
            esrc = se.x;
            float4 as = __ldg((const float4*)&g_asrc[(size_t)se.x * 4]);
            float4 ae = __ldg((const float4*)&g_ae[(size_t)se.y * 4]);
            aesum.x += ae.x; aesum.y += ae.y; aesum.z += ae.z; aesum.w += ae.w;
            float a0 = as.x + adst.x + ae.x, a1 = as.y + adst.y + ae.y;
            float a2 = as.z + adst.z + ae.z, a3 = as.w + adst.w + ae.w;
            a0 = (a0 >= 0.f) ? a0 : NEG * a0;  a1 = (a1 >= 0.f) ? a1 : NEG * a1;
            a2 = (a2 >= 0.f) ? a2 : NEG * a2;  a3 = (a3 >= 0.f) ? a3 : NEG * a3;
            w4 = make_float4(__expf(a0), __expf(a1), __expf(a2), __expf(a3));
        }
        // ---- Phase B: shfl-broadcast + 4-deep independent LDG.128 ----
        int p = 0;
        for (; p + 4 <= m; p += 4) {
            int s0 = __shfl_sync(0xffffffffu, esrc, p + 0);
            int s1 = __shfl_sync(0xffffffffu, esrc, p + 1);
            int s2 = __shfl_sync(0xffffffffu, esrc, p + 2);
            int s3 = __shfl_sync(0xffffffffu, esrc, p + 3);
            float4 hv0 = __ldg((const float4*)&g_h[(size_t)s0 * DINC + lane * 4]);
            float4 hv1 = __ldg((const float4*)&g_h[(size_t)s1 * DINC + lane * 4]);
            float4 hv2 = __ldg((const float4*)&g_h[(size_t)s2 * DINC + lane * 4]);
            float4 hv3 = __ldg((const float4*)&g_h[(size_t)s3 * DINC + lane * 4]);
            #pragma unroll
            for (int q = 0; q < 4; q++) {
                float wx = __shfl_sync(0xffffffffu, w4.x, p + q);
                float wy = __shfl_sync(0xffffffffu, w4.y, p + q);
                float wz = __shfl_sync(0xffffffffu, w4.z, p + q);
                float ww = __shfl_sync(0xffffffffu, w4.w, p + q);
                float wgt = (head & 2) ? ((head & 1) ? ww : wz)
                                       : ((head & 1) ? wy : wx);
                float4 hv = (q == 0) ? hv0 : (q == 1) ? hv1 : (q == 2) ? hv2 : hv3;
                acc.x += wgt * hv.x; acc.y += wgt * hv.y;
                acc.z += wgt * hv.z; acc.w += wgt * hv.w;
                den += wgt;
            }
        }
        for (; p < m; p++) {
            int s0 = __shfl_sync(0xffffffffu, esrc, p);
            float wx = __shfl_sync(0xffffffffu, w4.x, p);
            float wy = __shfl_sync(0xffffffffu, w4.y, p);
            float wz = __shfl_sync(0xffffffffu, w4.z, p);
            float ww = __shfl_sync(0xffffffffu, w4.w, p);
            float wgt = (head & 2) ? ((head & 1) ? ww : wz)
                                   : ((head & 1) ? wy : wx);
            float4 hv = __ldg((const float4*)&g_h[(size_t)s0 * DINC + lane * 4]);
            acc.x += wgt * hv.x; acc.y += wgt * hv.y;
            acc.z += wgt * hv.z; acc.w += wgt * hv.w;
            den += wgt;
        }
    }

    // ---- warp-reduce aesum (each edge counted once) ----
    #pragma unroll
    for (int o = 16; o > 0; o >>= 1) {
        aesum.x += __shfl_xor_sync(0xffffffffu, aesum.x, o);
        aesum.y += __shfl_xor_sync(0xffffffffu, aesum.y, o);
        aesum.z += __shfl_xor_sync(0xffffffffu, aesum.z, o);
        aesum.w += __shfl_xor_sync(0xffffffffu, aesum.w, o);
    }
    float aes = (head & 2) ? ((head & 1) ? aesum.w : aesum.z)
                           : ((head & 1) ? aesum.y : aesum.x);

    // ---- self-loop: ael = mean of incoming a_e ----
    float ael = aes / (float)max(deg, 1);
    float adst_h = (head & 2) ? ((head & 1) ? adst.w : adst.z)
                              : ((head & 1) ? adst.y : adst.x);
    float al = __ldg(&g_asrc[(size_t)n * 4 + head]) + adst_h + ael;
    al = (al >= 0.f) ? al : NEG * al;
    float ex = __expf(al);
    float4 hn = *(const float4*)&g_h[(size_t)n * DINC + lane * 4];
    acc.x += ex * hn.x; acc.y += ex * hn.y;
    acc.z += ex * hn.z; acc.w += ex * hn.w;
    den += ex;

    float rd = 1.f / den;
    float4 b4 = __ldg((const float4*)&bias[lane * 4]);
    float4 x4 = __ldg((const float4*)&x[(size_t)n * DINC + lane * 4]);
    float4 v = make_float4(acc.x * rd + b4.x + x4.x, acc.y * rd + b4.y + x4.y,
                           acc.z * rd + b4.z + x4.z, acc.w * rd + b4.w + x4.w);

    // ---- LayerNorm over 128 channels (warp reduce) ----
    float s  = v.x + v.y + v.z + v.w;
    float s2 = v.x * v.x + v.y * v.y + v.z * v.z + v.w * v.w;
    #pragma unroll
    for (int o = 16; o > 0; o >>= 1) {
        s  += __shfl_xor_sync(0xffffffffu, s, o);
        s2 += __shfl_xor_sync(0xffffffffu, s2, o);
    }
    float mu  = s * (1.f / 128.f);
    float var = s2 * (1.f / 128.f) - mu * mu;
    float r = rsqrtf(var + LNEPS);
    float4 g4 = __ldg((const float4*)&lng[lane * 4]);
    float4 o4 = __ldg((const float4*)&lnb[lane * 4]);
    float4 res = make_float4((v.x - mu) * r * g4.x + o4.x,
                             (v.y - mu) * r * g4.y + o4.y,
                             (v.z - mu) * r * g4.z + o4.z,
                             (v.w - mu) * r * g4.w + o4.w);
    *(float4*)&out[(size_t)n * DINC + lane * 4] = res;
}

// ---------------- launch -----------------------------------------------------
extern "C" void kernel_launch(void* const* d_in, const int* in_sizes, int n_in,
                              void* d_out, int out_size) {
    const float* x        = (const float*)d_in[0];
    const void*  ei       = (const void*)d_in[1];
    const float* eattr    = (const float*)d_in[2];
    const float* Wep      = (const float*)d_in[3];
    const float* bep      = (const float*)d_in[4];
    const float* Wlin     = (const float*)d_in[5];
    const float* Wedge    = (const float*)d_in[6];
    const float* att_src  = (const float*)d_in[7];
    const float* att_dst  = (const float*)d_in[8];
    const float* att_edge = (const float*)d_in[9];
    const float* bias     = (const float*)d_in[10];
    const float* lng      = (const float*)d_in[11];
    const float* lnb      = (const float*)d_in[12];
    float* out = (float*)d_out;

    int N = in_sizes[0] / DINC;
    int E = in_sizes[2] / ED;

    kinit<<<(N + 1023) / 1024, 1024>>>(Wedge, att_edge, N);        // 0
    k1_edge_mlp<<<(E + 255) / 256, 256>>>(eattr, ei, Wep, bep, E); // 1
    kscan<<<1, 1024>>>(N);                                         // 2
    kfill<<<(E + 255) / 256, 256>>>(E);                            // 3  <- ncu slot
    k2_gemm<<<592, 256>>>(x, Wlin, att_src, att_dst, N);           // 4
    k6_gather<<<(N + 7) / 8, 256>>>(out, x, bias, lng, lnb, N);    // 5
}